// round 6
// baseline (speedup 1.0000x reference)
#include <cuda_runtime.h>
#include <cstdint>

typedef unsigned long long u64;

// ---------- f32x2 / MUFU helpers ----------
__device__ __forceinline__ u64 ffma2(u64 a, u64 b, u64 c) {
    u64 d;
    asm("fma.rn.f32x2 %0, %1, %2, %3;" : "=l"(d) : "l"(a), "l"(b), "l"(c));
    return d;
}
__device__ __forceinline__ u64 fadd2(u64 a, u64 b) {
    u64 d;
    asm("add.rn.f32x2 %0, %1, %2;" : "=l"(d) : "l"(a), "l"(b));
    return d;
}
__device__ __forceinline__ u64 fmul2(u64 a, u64 b) {
    u64 d;
    asm("mul.rn.f32x2 %0, %1, %2;" : "=l"(d) : "l"(a), "l"(b));
    return d;
}
__device__ __forceinline__ u64 fpack(float x, float y) {
    u64 d;
    asm("mov.b64 %0, {%1, %2};" : "=l"(d) : "r"(__float_as_uint(x)), "r"(__float_as_uint(y)));
    return d;
}
__device__ __forceinline__ u64 fdup(float s) { return fpack(s, s); }
__device__ __forceinline__ void funpack(u64 v, float& x, float& y) {
    unsigned int a, b;
    asm("mov.b64 {%0, %1}, %2;" : "=r"(a), "=r"(b) : "l"(v));
    x = __uint_as_float(a);
    y = __uint_as_float(b);
}
__device__ __forceinline__ float fex2(float x) {
    float r; asm("ex2.approx.f32 %0, %1;" : "=f"(r) : "f"(x)); return r;
}
__device__ __forceinline__ float frcp(float x) {
    float r; asm("rcp.approx.f32 %0, %1;" : "=f"(r) : "f"(x)); return r;
}
__device__ __forceinline__ float ftanha(float x) {
    float r; asm("tanh.approx.f32 %0, %1;" : "=f"(r) : "f"(x)); return r;
}
__device__ __forceinline__ float fsig_exact(float x) {
    return frcp(1.0f + fex2(-1.44269504f * x));
}
__device__ __forceinline__ float ftanh_exact(float x) {
    return fmaf(-2.0f, frcp(1.0f + fex2(2.88539008f * x)), 1.0f);
}

// ---------- problem constants ----------
constexpr int BATCH = 8192;
constexpr int HID   = 10;
constexpr int STEPS = 512;
constexpr int PAIRS = BATCH / 2;       // 4096
constexpr int WPB   = 10;
constexpr int TPB   = WPB * 32;        // 320
constexpr int GRID  = 148;             // exactly 1 block / SM
constexpr int TOTW  = GRID * WPB;      // 1480 warps; pair slot s of warp g -> g + s*1480

// Folded weights: G = w_ih @ l2_w @ l1_w (30x10), d = w_ih@l2_b + (w_ih@l2_w)@l1_b + b_ih (30)
__device__ float g_G[300];
__device__ float g_d[30];
// sink area for lanes without a valid pair (branch-free stores, chunk-dec = 0)
__device__ float g_sink[16384];

// ---------- prep kernel: fold the input path ----------
__global__ void prep_kernel(const float* __restrict__ w_ih,
                            const float* __restrict__ b_ih,
                            const float* __restrict__ l1_w,
                            const float* __restrict__ l1_b,
                            const float* __restrict__ l2_w,
                            const float* __restrict__ l2_b) {
    __shared__ float Wm[300]; // w_ih @ l2_w : (30,10)
    int t = threadIdx.x;
    if (t < 300) {
        int r = t / 10, m = t % 10;
        float s = 0.0f;
        for (int i = 0; i < 64; i++) s += w_ih[r * 64 + i] * l2_w[i * 10 + m];
        Wm[t] = s;
    }
    __syncthreads();
    if (t < 300) {
        int r = t / 10, k = t % 10;
        float g = 0.0f;
        for (int m = 0; m < 10; m++) g += Wm[r * 10 + m] * l1_w[m * 10 + k];
        g_G[t] = g;
    } else if (t < 330) {
        int r = t - 300;
        float s = b_ih[r];
        for (int i = 0; i < 64; i++) s += w_ih[r * 64 + i] * l2_b[i];
        for (int m = 0; m < 10; m++) s += Wm[r * 10 + m] * l1_b[m];
        g_d[r] = s;
    }
}

// One GRU step. RB = buffer read this step (compile-time), OFS = store offset
// (compile-time immediate, in floats). Stores o_{t-1} (computed from the h
// loaded this step), then computes h_t and writes it to buffer RB^1.
#define GRU_STEP(RB, OFS)                                                      \
  do {                                                                        \
    __syncwarp();                                                             \
    const ulonglong2* hp =                                                    \
        reinterpret_cast<const ulonglong2*>(&hsh[w][RB][dd][0]);              \
    const ulonglong2 h01 = hp[0], h23 = hp[1], h45 = hp[2],                   \
                     h67 = hp[3], h89 = hp[4];                                \
    u64 aR = vbr, aR2 = ZERO2, aH = vbhn, aH2 = ZERO2;                        \
    u64 aZ = vbz, aI = vbin, aO = vl1b;                                       \
    aR = ffma2(Mr[0], h01.x, aR);   aR2 = ffma2(Mr[1], h01.y, aR2);           \
    aH = ffma2(Wn[0], h01.x, aH);   aH2 = ffma2(Wn[1], h01.y, aH2);           \
    aR = ffma2(Mr[2], h23.x, aR);   aR2 = ffma2(Mr[3], h23.y, aR2);           \
    aH = ffma2(Wn[2], h23.x, aH);   aH2 = ffma2(Wn[3], h23.y, aH2);           \
    aR = ffma2(Mr[4], h45.x, aR);   aR2 = ffma2(Mr[5], h45.y, aR2);           \
    aH = ffma2(Wn[4], h45.x, aH);   aH2 = ffma2(Wn[5], h45.y, aH2);           \
    aR = ffma2(Mr[6], h67.x, aR);   aR2 = ffma2(Mr[7], h67.y, aR2);           \
    aH = ffma2(Wn[6], h67.x, aH);   aH2 = ffma2(Wn[7], h67.y, aH2);           \
    aR = ffma2(Mr[8], h89.x, aR);   aR2 = ffma2(Mr[9], h89.y, aR2);           \
    aH = ffma2(Wn[8], h89.x, aH);   aH2 = ffma2(Wn[9], h89.y, aH2);           \
    aR = fadd2(aR, aR2);                                                      \
    aH = fadd2(aH, aH2);                                                      \
    /* r-tanh first: it is on the serial path */                              \
    float rX, rY;                                                             \
    funpack(aR, rX, rY);                                                      \
    const float tRx = ftanha(rX), tRy = ftanha(rY);                           \
    aZ = ffma2(Mz[0], h01.x, aZ);   aZ = ffma2(Mz[1], h01.y, aZ);             \
    aZ = ffma2(Mz[2], h23.x, aZ);   aZ = ffma2(Mz[3], h23.y, aZ);             \
    aZ = ffma2(Mz[4], h45.x, aZ);   aZ = ffma2(Mz[5], h45.y, aZ);             \
    aZ = ffma2(Mz[6], h67.x, aZ);   aZ = ffma2(Mz[7], h67.y, aZ);             \
    aZ = ffma2(Mz[8], h89.x, aZ);   aZ = ffma2(Mz[9], h89.y, aZ);             \
    aI = ffma2(Gn[0], h01.x, aI);   aI = ffma2(Gn[1], h01.y, aI);             \
    aI = ffma2(Gn[2], h23.x, aI);   aI = ffma2(Gn[3], h23.y, aI);             \
    aI = ffma2(Gn[4], h45.x, aI);   aI = ffma2(Gn[5], h45.y, aI);             \
    aI = ffma2(Gn[6], h67.x, aI);   aI = ffma2(Gn[7], h67.y, aI);             \
    aI = ffma2(Gn[8], h89.x, aI);   aI = ffma2(Gn[9], h89.y, aI);             \
    aO = ffma2(L1[0], h01.x, aO);   aO = ffma2(L1[1], h01.y, aO);             \
    aO = ffma2(L1[2], h23.x, aO);   aO = ffma2(L1[3], h23.y, aO);             \
    aO = ffma2(L1[4], h45.x, aO);   aO = ffma2(L1[5], h45.y, aO);             \
    aO = ffma2(L1[6], h67.x, aO);   aO = ffma2(L1[7], h67.y, aO);             \
    aO = ffma2(L1[8], h89.x, aO);   aO = ffma2(L1[9], h89.y, aO);             \
    /* helper terms (parallel with r-tanh): arg = tR*(0.5 aH) + (aI+0.5 aH) */\
    const u64 uv = ffma2(HALF2, aH, aI);                                      \
    const u64 vv = fmul2(HALF2, aH);                                          \
    const u64 argv = ffma2(fpack(tRx, tRy), vv, uv);                          \
    /* store o_{t-1} */                                                       \
    {                                                                         \
      float ox, oy;                                                           \
      funpack(aO, ox, oy);                                                    \
      o0c[OFS] = ox; o1c[OFS] = oy;                                           \
    }                                                                         \
    /* z = 0.5 + 0.5 tanh(aZ) (pre-scaled) */                                 \
    float zX, zY;                                                             \
    funpack(aZ, zX, zY);                                                      \
    const u64 zv = ffma2(HALF2, fpack(ftanha(zX), ftanha(zY)), HALF2);        \
    /* n = tanh(arg) */                                                       \
    float nX, nY;                                                             \
    funpack(argv, nX, nY);                                                    \
    const u64 nv = fpack(ftanha(nX), ftanha(nY));                             \
    /* h' = n + z*(h - n) */                                                  \
    hv = ffma2(zv, ffma2(nv, NEG12, hv), nv);                                 \
    hsh[w][(RB) ^ 1][p][j] = hv;                                              \
  } while (0)

// ---------- main recurrence kernel ----------
// thread = (batch pair, gate dim j); pair = 2 batch elements in f32x2.
// 3 pairs per warp on lanes 0..29; lanes 30/31 shadow slot 0 and store to a
// sink. 1480 warps = exactly 10 warps on each of 148 SMs.
// h exchanged through a warp-local double-buffered shared row; one __syncwarp
// per step. sigma(a)=0.5+0.5*tanh(a/2) with the 0.5 folded into weights; all
// activations tanh.approx. Step loop unrolled x4 with immediate store offsets.
__global__ void __launch_bounds__(TPB) gru_kernel(
    const float* __restrict__ hidden,
    const float* __restrict__ w_hh,
    const float* __restrict__ b_ih,
    const float* __restrict__ b_hh,
    const float* __restrict__ l1_w,
    const float* __restrict__ l1_b,
    float* __restrict__ out) {
    __shared__ alignas(16) u64 hsh[WPB][2][4][HID];

    const int lane = threadIdx.x & 31;
    const int w    = threadIdx.x >> 5;
    const int p    = lane / 10;            // 0..2 pair slots, 3 = spare lanes
    const int dd   = (p < 3) ? p : 0;      // spares read slot 0
    const int j    = lane - p * 10;        // 0..9 (spares: 0..1)
    const int g    = blockIdx.x * WPB + w;
    const int pairIdx = g + dd * TOTW;     // round-robin pair map
    const bool valid  = (p < 3) && (pairIdx < PAIRS);
    const int bb      = valid ? pairIdx * 2 : 0;

    // per-thread folded + scaled weight rows, duplicated into both halves
    u64 Mr[10], Mz[10], Gn[10], Wn[10], L1[10];
#pragma unroll
    for (int k = 0; k < 10; k++) {
        Mr[k] = fdup(0.5f * (w_hh[j * 10 + k]        + g_G[j * 10 + k]));
        Mz[k] = fdup(0.5f * (w_hh[(10 + j) * 10 + k] + g_G[(10 + j) * 10 + k]));
        Gn[k] = fdup(g_G[(20 + j) * 10 + k]);
        Wn[k] = fdup(w_hh[(20 + j) * 10 + k]);
        L1[k] = fdup(l1_w[j * 10 + k]);
    }
    const u64 vbr  = fdup(0.5f * (b_hh[j]      + g_d[j]));
    const u64 vbz  = fdup(0.5f * (b_hh[10 + j] + g_d[10 + j]));
    const u64 vbin = fdup(g_d[20 + j]);
    const u64 vbhn = fdup(b_hh[20 + j]);
    const u64 vl1b = fdup(l1_b[j]);
    const u64 ZERO2 = 0ULL;
    const u64 HALF2 = fdup(0.5f);
    const u64 NEG12 = fdup(-1.0f);

    u64 hv = fpack(hidden[bb * 10 + j], hidden[(bb + 1) * 10 + j]);

    hsh[w][0][p][j] = hv;
    __syncwarp();

    // peeled step 0: x0 = 0 -> gi = b_ih exactly. Exact activations (once).
    {
        float hx, hy;
        funpack(hv, hx, hy);
        float aRx = b_hh[j] + b_ih[j];
        float aZx = b_hh[10 + j] + b_ih[10 + j];
        float aRy = aRx, aZy = aZx;
        float aHx = b_hh[20 + j], aHy = aHx;
#pragma unroll
        for (int k = 0; k < 10; k++) {
            float kx, ky;
            funpack(hsh[w][0][dd][k], kx, ky);
            float wr = w_hh[j * 10 + k];
            float wz = w_hh[(10 + j) * 10 + k];
            float wn = w_hh[(20 + j) * 10 + k];
            aRx = fmaf(wr, kx, aRx); aRy = fmaf(wr, ky, aRy);
            aZx = fmaf(wz, kx, aZx); aZy = fmaf(wz, ky, aZy);
            aHx = fmaf(wn, kx, aHx); aHy = fmaf(wn, ky, aHy);
        }
        float inb = b_ih[20 + j];
        float rx = fsig_exact(aRx), ry = fsig_exact(aRy);
        float zx = fsig_exact(aZx), zy = fsig_exact(aZy);
        float nx = ftanh_exact(fmaf(rx, aHx, inb));
        float ny = ftanh_exact(fmaf(ry, aHy, inb));
        hx = fmaf(zx, hx - nx, nx);
        hy = fmaf(zy, hy - ny, ny);
        hv = fpack(hx, hy);
    }
    hsh[w][1][p][j] = hv;

    // REVERSE output: o_t -> row (511 - t); at iter t we emit o_{t-1}.
    // Chunk base pointers, decremented by 4 rows per chunk (0 for sink lanes).
    float *o0c, *o1c;
    int dec4;
    if (valid) {
        o0c = out + (size_t)bb * (STEPS * HID) + (size_t)(STEPS - 1) * HID + j;
        o1c = o0c + (size_t)STEPS * HID;
        dec4 = 4 * HID;
    } else {
        o0c = g_sink + 64 + j;
        o1c = g_sink + 128 + j;
        dec4 = 0;
    }

    // t = 1..508 in 127 chunks of 4 (buffers alternate 1,0,1,0)
#pragma unroll 1
    for (int c = 0; c < 127; ++c) {
        GRU_STEP(1, 0);
        GRU_STEP(0, -10);
        GRU_STEP(1, -20);
        GRU_STEP(0, -30);
        o0c -= dec4;
        o1c -= dec4;
    }
    // tail: t = 509, 510, 511 (parities 1, 0, 1)
    GRU_STEP(1, 0);
    GRU_STEP(0, -10);
    GRU_STEP(1, -20);

    // epilogue: o_511 -> row 0 (h_512 sits in buffer 0 after t = 511)
    __syncwarp();
    {
        u64 aO = vl1b;
#pragma unroll
        for (int k = 0; k < 10; k++) aO = ffma2(L1[k], hsh[w][0][dd][k], aO);
        float ox, oy;
        funpack(aO, ox, oy);
        o0c[-30] = ox;
        o1c[-30] = oy;
    }
}

extern "C" void kernel_launch(void* const* d_in, const int* in_sizes, int n_in,
                              void* d_out, int out_size) {
    const float* hidden = (const float*)d_in[0];
    const float* w_ih   = (const float*)d_in[1];
    const float* w_hh   = (const float*)d_in[2];
    const float* b_ih   = (const float*)d_in[3];
    const float* b_hh   = (const float*)d_in[4];
    const float* l1_w   = (const float*)d_in[5];
    const float* l1_b   = (const float*)d_in[6];
    const float* l2_w   = (const float*)d_in[7];
    const float* l2_b   = (const float*)d_in[8];

    prep_kernel<<<1, 384>>>(w_ih, b_ih, l1_w, l1_b, l2_w, l2_b);
    gru_kernel<<<GRID, TPB>>>(hidden, w_hh, b_ih, b_hh, l1_w, l1_b, (float*)d_out);
}

// round 7
// speedup vs baseline: 1.2613x; 1.2613x over previous
#include <cuda_runtime.h>
#include <cstdint>

typedef unsigned long long u64;

// ---------- f32x2 / MUFU helpers ----------
__device__ __forceinline__ u64 ffma2(u64 a, u64 b, u64 c) {
    u64 d;
    asm("fma.rn.f32x2 %0, %1, %2, %3;" : "=l"(d) : "l"(a), "l"(b), "l"(c));
    return d;
}
__device__ __forceinline__ u64 fadd2(u64 a, u64 b) {
    u64 d;
    asm("add.rn.f32x2 %0, %1, %2;" : "=l"(d) : "l"(a), "l"(b));
    return d;
}
__device__ __forceinline__ u64 fpack(float x, float y) {
    u64 d;
    asm("mov.b64 %0, {%1, %2};" : "=l"(d) : "r"(__float_as_uint(x)), "r"(__float_as_uint(y)));
    return d;
}
__device__ __forceinline__ u64 fdup(float s) { return fpack(s, s); }
__device__ __forceinline__ void funpack(u64 v, float& x, float& y) {
    unsigned int a, b;
    asm("mov.b64 {%0, %1}, %2;" : "=r"(a), "=r"(b) : "l"(v));
    x = __uint_as_float(a);
    y = __uint_as_float(b);
}
__device__ __forceinline__ float fex2(float x) {
    float r; asm("ex2.approx.f32 %0, %1;" : "=f"(r) : "f"(x)); return r;
}
__device__ __forceinline__ float frcp(float x) {
    float r; asm("rcp.approx.f32 %0, %1;" : "=f"(r) : "f"(x)); return r;
}
__device__ __forceinline__ float ftanha(float x) {
    float r; asm("tanh.approx.f32 %0, %1;" : "=f"(r) : "f"(x)); return r;
}
__device__ __forceinline__ float fsig_exact(float x) {
    return frcp(1.0f + fex2(-1.44269504f * x));
}
__device__ __forceinline__ float ftanh_exact(float x) {
    return fmaf(-2.0f, frcp(1.0f + fex2(2.88539008f * x)), 1.0f);
}

// ---------- problem constants ----------
constexpr int BATCH = 8192;
constexpr int HID   = 10;
constexpr int STEPS = 512;
constexpr int PAIRS = BATCH / 2;       // 4096
constexpr int WPB   = 14;
constexpr int TPB   = WPB * 32;        // 448
constexpr int GRID  = 148;             // exactly 1 block / SM, 14 warps each
constexpr int TOTW  = GRID * WPB;      // 2072 warps; pair slot s of warp g -> g + s*2072

// Folded weights: G = w_ih @ l2_w @ l1_w (30x10), d = w_ih@l2_b + (w_ih@l2_w)@l1_b + b_ih (30)
__device__ float g_G[300];
__device__ float g_d[30];
// sink rows for lanes without a valid batch pair (branch-free stores)
__device__ float g_sink[2 * STEPS * HID];

// ---------- prep kernel: fold the input path ----------
__global__ void prep_kernel(const float* __restrict__ w_ih,
                            const float* __restrict__ b_ih,
                            const float* __restrict__ l1_w,
                            const float* __restrict__ l1_b,
                            const float* __restrict__ l2_w,
                            const float* __restrict__ l2_b) {
    __shared__ float Wm[300]; // w_ih @ l2_w : (30,10)
    int t = threadIdx.x;
    if (t < 300) {
        int r = t / 10, m = t % 10;
        float s = 0.0f;
        for (int i = 0; i < 64; i++) s += w_ih[r * 64 + i] * l2_w[i * 10 + m];
        Wm[t] = s;
    }
    __syncthreads();
    if (t < 300) {
        int r = t / 10, k = t % 10;
        float g = 0.0f;
        for (int m = 0; m < 10; m++) g += Wm[r * 10 + m] * l1_w[m * 10 + k];
        g_G[t] = g;
    } else if (t < 330) {
        int r = t - 300;
        float s = b_ih[r];
        for (int i = 0; i < 64; i++) s += w_ih[r * 64 + i] * l2_b[i];
        for (int m = 0; m < 10; m++) s += Wm[r * 10 + m] * l1_b[m];
        g_d[r] = s;
    }
}

// ---------- main recurrence kernel ----------
// thread = (batch pair, gate dim j); pair = 2 batch elements in f32x2.
// ONLY 2 pairs per warp (lanes 0..19) -> 2048 active warps (13.8/SM,
// 3.45/SMSP) for latency hiding at unchanged per-warp instruction count.
// Lanes 20..31 shadow pair-slot 0 (identical stream; write smem slots 2/3 and
// a sink row). h exchanged via warp-local double-buffered shared rows
// (LDS.128), one __syncwarp per step. sigma(a)=0.5+0.5*tanh(a/2) with the 0.5
// folded into the r/z weights; all activations tanh.approx.
__global__ void __launch_bounds__(TPB) gru_kernel(
    const float* __restrict__ hidden,
    const float* __restrict__ w_hh,
    const float* __restrict__ b_ih,
    const float* __restrict__ b_hh,
    const float* __restrict__ l1_w,
    const float* __restrict__ l1_b,
    float* __restrict__ out) {
    __shared__ alignas(16) u64 hsh[WPB][2][4][HID];

    const int lane = threadIdx.x & 31;
    const int w    = threadIdx.x >> 5;
    const int p    = lane / 10;            // 0,1 = real pair slots; 2,3 = spares
    const int dd   = (p < 2) ? p : 0;      // spares read slot 0
    const int j    = lane - p * 10;        // 0..9 (p=3 spares: 0..1)
    const int g    = blockIdx.x * WPB + w;
    const int pairIdx = g + dd * TOTW;     // round-robin pair map
    const bool valid  = (p < 2) && (pairIdx < PAIRS);
    const int bb      = valid ? pairIdx * 2 : 0;

    // per-thread folded + scaled weight rows, duplicated into both f32x2 halves
    u64 Mr[10], Mz[10], Gn[10], Wn[10], L1[10];
#pragma unroll
    for (int k = 0; k < 10; k++) {
        Mr[k] = fdup(0.5f * (w_hh[j * 10 + k]        + g_G[j * 10 + k]));
        Mz[k] = fdup(0.5f * (w_hh[(10 + j) * 10 + k] + g_G[(10 + j) * 10 + k]));
        Gn[k] = fdup(g_G[(20 + j) * 10 + k]);
        Wn[k] = fdup(w_hh[(20 + j) * 10 + k]);
        L1[k] = fdup(l1_w[j * 10 + k]);
    }
    const u64 vbr  = fdup(0.5f * (b_hh[j]      + g_d[j]));
    const u64 vbz  = fdup(0.5f * (b_hh[10 + j] + g_d[10 + j]));
    const u64 vbin = fdup(g_d[20 + j]);
    const u64 vbhn = fdup(b_hh[20 + j]);
    const u64 vl1b = fdup(l1_b[j]);
    const u64 ZERO2 = 0ULL;
    const u64 HALF2 = fdup(0.5f);
    const u64 NEG12 = fdup(-1.0f);

    float hx = hidden[bb * 10 + j];
    float hy = hidden[(bb + 1) * 10 + j];

    hsh[w][0][p][j] = fpack(hx, hy);
    __syncwarp();

    // peeled step 0: x0 = 0 -> gi = b_ih exactly (no G*h term). Exact activations.
    {
        float aRx = b_hh[j] + b_ih[j];
        float aZx = b_hh[10 + j] + b_ih[10 + j];
        float aRy = aRx, aZy = aZx;
        float aHx = b_hh[20 + j], aHy = aHx;
#pragma unroll
        for (int k = 0; k < 10; k++) {
            float kx, ky;
            funpack(hsh[w][0][dd][k], kx, ky);
            float wr = w_hh[j * 10 + k];
            float wz = w_hh[(10 + j) * 10 + k];
            float wn = w_hh[(20 + j) * 10 + k];
            aRx = fmaf(wr, kx, aRx); aRy = fmaf(wr, ky, aRy);
            aZx = fmaf(wz, kx, aZx); aZy = fmaf(wz, ky, aZy);
            aHx = fmaf(wn, kx, aHx); aHy = fmaf(wn, ky, aHy);
        }
        float inb = b_ih[20 + j];
        float rx = fsig_exact(aRx), ry = fsig_exact(aRy);
        float zx = fsig_exact(aZx), zy = fsig_exact(aZy);
        float nx = ftanh_exact(fmaf(rx, aHx, inb));
        float ny = ftanh_exact(fmaf(ry, aHy, inb));
        hx = fmaf(zx, hx - nx, nx);
        hy = fmaf(zy, hy - ny, ny);
    }
    u64 hv = fpack(hx, hy);
    hsh[w][1][p][j] = hv;

    // REVERSE output: o_t -> row (511 - t); at iter t we emit o_{t-1} -> row 512 - t
    // invalid lanes walk a sink row instead (branch-free stores, in-bounds)
    float* o0;
    float* o1;
    if (valid) {
        o0 = out + (size_t)bb * (STEPS * HID) + (STEPS - 1) * HID + j;
        o1 = out + (size_t)(bb + 1) * (STEPS * HID) + (STEPS - 1) * HID + j;
    } else {
        o0 = g_sink + (STEPS - 1) * HID + j;
        o1 = g_sink + STEPS * HID + (STEPS - 1) * HID + j;
    }

#pragma unroll 2
    for (int t = 1; t < STEPS; ++t) {
        __syncwarp();
        const int rb = t & 1;
        const ulonglong2* hp = reinterpret_cast<const ulonglong2*>(&hsh[w][rb][dd][0]);
        // split chains for the two accumulators on the serial path
        u64 aR = vbr, aR2 = ZERO2;
        u64 aH = vbhn, aH2 = ZERO2;
        u64 aZ = vbz, aI = vbin, aO = vl1b;
#pragma unroll
        for (int kk = 0; kk < 5; kk++) {
            const ulonglong2 hh = hp[kk];           // LDS.128: h[2kk], h[2kk+1]
            const int k = 2 * kk;
            aR  = ffma2(Mr[k], hh.x, aR);   aR2 = ffma2(Mr[k + 1], hh.y, aR2);
            aH  = ffma2(Wn[k], hh.x, aH);   aH2 = ffma2(Wn[k + 1], hh.y, aH2);
            aZ  = ffma2(Mz[k], hh.x, aZ);   aZ  = ffma2(Mz[k + 1], hh.y, aZ);
            aI  = ffma2(Gn[k], hh.x, aI);   aI  = ffma2(Gn[k + 1], hh.y, aI);
            aO  = ffma2(L1[k], hh.x, aO);   aO  = ffma2(L1[k + 1], hh.y, aO);
        }
        aR = fadd2(aR, aR2);
        aH = fadd2(aH, aH2);

        // store o_{t-1} (aO computed from h_t which is h_new of step t-1)
        {
            float ox, oy;
            funpack(aO, ox, oy);
            *o0 = ox; *o1 = oy;
            o0 -= HID; o1 -= HID;
        }

        // r = 0.5 + 0.5*tanh(aR), z likewise (aR/aZ pre-scaled by 0.5)
        float aRx, aRy, aZx, aZy;
        funpack(aR, aRx, aRy);
        funpack(aZ, aZx, aZy);
        u64 rv = ffma2(HALF2, fpack(ftanha(aRx), ftanha(aRy)), HALF2);
        u64 zv = ffma2(HALF2, fpack(ftanha(aZx), ftanha(aZy)), HALF2);

        // n = tanh(aI + r*aH)
        u64 argv = ffma2(rv, aH, aI);
        float ax, ay;
        funpack(argv, ax, ay);
        u64 nv = fpack(ftanha(ax), ftanha(ay));

        // h' = n + z*(h - n)
        u64 dv = ffma2(nv, NEG12, hv);
        hv = ffma2(zv, dv, nv);
        hsh[w][rb ^ 1][p][j] = hv;
    }

    // epilogue: o_511 -> row 0 (h_512 sits in buffer 0 after t=511)
    __syncwarp();
    {
        u64 aO = vl1b;
#pragma unroll
        for (int k = 0; k < 10; k++) aO = ffma2(L1[k], hsh[w][0][dd][k], aO);
        float ox, oy;
        funpack(aO, ox, oy);
        *o0 = ox; *o1 = oy;
    }
}

extern "C" void kernel_launch(void* const* d_in, const int* in_sizes, int n_in,
                              void* d_out, int out_size) {
    const float* hidden = (const float*)d_in[0];
    const float* w_ih   = (const float*)d_in[1];
    const float* w_hh   = (const float*)d_in[2];
    const float* b_ih   = (const float*)d_in[3];
    const float* b_hh   = (const float*)d_in[4];
    const float* l1_w   = (const float*)d_in[5];
    const float* l1_b   = (const float*)d_in[6];
    const float* l2_w   = (const float*)d_in[7];
    const float* l2_b   = (const float*)d_in[8];

    prep_kernel<<<1, 384>>>(w_ih, b_ih, l1_w, l1_b, l2_w, l2_b);
    gru_kernel<<<GRID, TPB>>>(hidden, w_hh, b_ih, b_hh, l1_w, l1_b, (float*)d_out);
}

// round 8
// speedup vs baseline: 1.7302x; 1.3718x over previous
#include <cuda_runtime.h>
#include <cstdint>

typedef unsigned long long u64;

// ---------- f32x2 / MUFU helpers ----------
__device__ __forceinline__ u64 ffma2(u64 a, u64 b, u64 c) {
    u64 d;
    asm("fma.rn.f32x2 %0, %1, %2, %3;" : "=l"(d) : "l"(a), "l"(b), "l"(c));
    return d;
}
__device__ __forceinline__ u64 fpack(float x, float y) {
    u64 d;
    asm("mov.b64 %0, {%1, %2};" : "=l"(d) : "r"(__float_as_uint(x)), "r"(__float_as_uint(y)));
    return d;
}
__device__ __forceinline__ u64 fdup(float s) { return fpack(s, s); }
__device__ __forceinline__ void funpack(u64 v, float& x, float& y) {
    unsigned int a, b;
    asm("mov.b64 {%0, %1}, %2;" : "=r"(a), "=r"(b) : "l"(v));
    x = __uint_as_float(a);
    y = __uint_as_float(b);
}
__device__ __forceinline__ float fex2(float x) {
    float r; asm("ex2.approx.f32 %0, %1;" : "=f"(r) : "f"(x)); return r;
}
__device__ __forceinline__ float frcp(float x) {
    float r; asm("rcp.approx.f32 %0, %1;" : "=f"(r) : "f"(x)); return r;
}
__device__ __forceinline__ float ftanha(float x) {
    float r; asm("tanh.approx.f32 %0, %1;" : "=f"(r) : "f"(x)); return r;
}
__device__ __forceinline__ float fsig_exact(float x) {
    return frcp(1.0f + fex2(-1.44269504f * x));
}
__device__ __forceinline__ float ftanh_exact(float x) {
    return fmaf(-2.0f, frcp(1.0f + fex2(2.88539008f * x)), 1.0f);
}

// ---------- problem constants ----------
constexpr int BATCH = 8192;
constexpr int HID   = 10;
constexpr int STEPS = 512;
constexpr int PAIRS = BATCH / 2;       // 4096
constexpr int WPB   = 10;
constexpr int TPB   = WPB * 32;        // 320
constexpr int GRID  = 148;             // exactly 1 block / SM
constexpr int TOTW  = GRID * WPB;      // 1480 warps; pair slot s of warp g -> g + s*1480

// Folded weights: G = w_ih @ l2_w @ l1_w (30x10), d = w_ih@l2_b + (w_ih@l2_w)@l1_b + b_ih (30)
__device__ float g_G[300];
__device__ float g_d[30];
// sink rows for lanes without a valid batch pair (branch-free stores, full walk)
__device__ float g_sink[2 * STEPS * HID];

// ---------- prep kernel: fold the input path ----------
__global__ void prep_kernel(const float* __restrict__ w_ih,
                            const float* __restrict__ b_ih,
                            const float* __restrict__ l1_w,
                            const float* __restrict__ l1_b,
                            const float* __restrict__ l2_w,
                            const float* __restrict__ l2_b) {
    __shared__ float Wm[300]; // w_ih @ l2_w : (30,10)
    int t = threadIdx.x;
    if (t < 300) {
        int r = t / 10, m = t % 10;
        float s = 0.0f;
        for (int i = 0; i < 64; i++) s += w_ih[r * 64 + i] * l2_w[i * 10 + m];
        Wm[t] = s;
    }
    __syncthreads();
    if (t < 300) {
        int r = t / 10, k = t % 10;
        float g = 0.0f;
        for (int m = 0; m < 10; m++) g += Wm[r * 10 + m] * l1_w[m * 10 + k];
        g_G[t] = g;
    } else if (t < 330) {
        int r = t - 300;
        float s = b_ih[r];
        for (int i = 0; i < 64; i++) s += w_ih[r * 64 + i] * l2_b[i];
        for (int m = 0; m < 10; m++) s += Wm[r * 10 + m] * l1_b[m];
        g_d[r] = s;
    }
}

// ---------- main recurrence kernel ----------
// thread = (batch pair, gate dim j); pair = 2 batch elements in f32x2 for the
// five dot products (50 FFMA2 = the algebraic floor). Everything AFTER the
// dots is scalar fp32: unpacking 64-bit accumulators is free (register
// aliasing) while packing scalars costs MOVs. h carried as 2 scalars, written
// with one st.shared.v2.f32. 3 pairs per warp on lanes 0..29; lanes 30/31
// shadow slot 0 and store to a sink. One __syncwarp per step. All activations
// tanh.approx: sigma(a) = 0.5 + 0.5*tanh(a/2) with the 0.5 pre-folded into
// the r/z weights. Issue-bound design: minimize warp-instructions per step.
__global__ void __launch_bounds__(TPB) gru_kernel(
    const float* __restrict__ hidden,
    const float* __restrict__ w_hh,
    const float* __restrict__ b_ih,
    const float* __restrict__ b_hh,
    const float* __restrict__ l1_w,
    const float* __restrict__ l1_b,
    float* __restrict__ out) {
    __shared__ alignas(16) u64 hsh[WPB][2][4][HID];

    const int lane = threadIdx.x & 31;
    const int w    = threadIdx.x >> 5;
    const int p    = lane / 10;            // 0..2 pair slots, 3 = spare lanes
    const int dd   = (p < 3) ? p : 0;      // spares read slot 0
    const int j    = lane - p * 10;        // 0..9 (spares: 0..1)
    const int g    = blockIdx.x * WPB + w;
    const int pairIdx = g + dd * TOTW;     // round-robin pair map
    const bool valid  = (p < 3) && (pairIdx < PAIRS);
    const int bb      = valid ? pairIdx * 2 : 0;

    // per-thread folded + scaled weight rows, duplicated into both f32x2 halves
    u64 Mr[10], Mz[10], Gn[10], Wn[10], L1[10];
#pragma unroll
    for (int k = 0; k < 10; k++) {
        Mr[k] = fdup(0.5f * (w_hh[j * 10 + k]        + g_G[j * 10 + k]));
        Mz[k] = fdup(0.5f * (w_hh[(10 + j) * 10 + k] + g_G[(10 + j) * 10 + k]));
        Gn[k] = fdup(g_G[(20 + j) * 10 + k]);
        Wn[k] = fdup(w_hh[(20 + j) * 10 + k]);
        L1[k] = fdup(l1_w[j * 10 + k]);
    }
    const u64 vbr  = fdup(0.5f * (b_hh[j]      + g_d[j]));
    const u64 vbz  = fdup(0.5f * (b_hh[10 + j] + g_d[10 + j]));
    const u64 vbin = fdup(g_d[20 + j]);
    const u64 vbhn = fdup(b_hh[20 + j]);
    const u64 vl1b = fdup(l1_b[j]);

    float hx = hidden[bb * 10 + j];
    float hy = hidden[(bb + 1) * 10 + j];

    // smem addresses for this thread's h slot (write) and group row (read)
    u64* wr0 = &hsh[w][0][p][j];
    u64* wr1 = &hsh[w][1][p][j];
    const ulonglong2* rd0 = reinterpret_cast<const ulonglong2*>(&hsh[w][0][dd][0]);
    const ulonglong2* rd1 = reinterpret_cast<const ulonglong2*>(&hsh[w][1][dd][0]);

    *wr0 = fpack(hx, hy);
    __syncwarp();

    // peeled step 0: x0 = 0 -> gi = b_ih exactly (no G*h term). Exact activations.
    {
        float aRx = b_hh[j] + b_ih[j];
        float aZx = b_hh[10 + j] + b_ih[10 + j];
        float aRy = aRx, aZy = aZx;
        float aHx = b_hh[20 + j], aHy = aHx;
#pragma unroll
        for (int k = 0; k < 10; k++) {
            float kx, ky;
            funpack(hsh[w][0][dd][k], kx, ky);
            float wr = w_hh[j * 10 + k];
            float wz = w_hh[(10 + j) * 10 + k];
            float wn = w_hh[(20 + j) * 10 + k];
            aRx = fmaf(wr, kx, aRx); aRy = fmaf(wr, ky, aRy);
            aZx = fmaf(wz, kx, aZx); aZy = fmaf(wz, ky, aZy);
            aHx = fmaf(wn, kx, aHx); aHy = fmaf(wn, ky, aHy);
        }
        float inb = b_ih[20 + j];
        float rx = fsig_exact(aRx), ry = fsig_exact(aRy);
        float zx = fsig_exact(aZx), zy = fsig_exact(aZy);
        float nx = ftanh_exact(fmaf(rx, aHx, inb));
        float ny = ftanh_exact(fmaf(ry, aHy, inb));
        hx = fmaf(zx, hx - nx, nx);
        hy = fmaf(zy, hy - ny, ny);
    }
    asm volatile("st.shared.v2.f32 [%0], {%1, %2};" ::
                 "l"(wr1), "f"(hx), "f"(hy));

    // REVERSE output: o_t -> row (511 - t); at iter t we emit o_{t-1}.
    // Invalid lanes walk sink rows (branch-free, same full walk, in-bounds).
    float* o0;
    float* o1;
    if (valid) {
        o0 = out + (size_t)bb * (STEPS * HID) + (STEPS - 1) * HID + j;
        o1 = out + (size_t)(bb + 1) * (STEPS * HID) + (STEPS - 1) * HID + j;
    } else {
        o0 = g_sink + (STEPS - 1) * HID + j;
        o1 = g_sink + STEPS * HID + (STEPS - 1) * HID + j;
    }

    // one GRU step: read buffer RD, write buffer WRP, store o at offset OFS
#define STEP(RD, WRP, OFS)                                                    \
  do {                                                                        \
    __syncwarp();                                                             \
    const ulonglong2 h01 = (RD)[0], h23 = (RD)[1], h45 = (RD)[2],             \
                     h67 = (RD)[3], h89 = (RD)[4];                            \
    u64 aR = vbr, aZ = vbz, aI = vbin, aH = vbhn, aO = vl1b;                  \
    aR = ffma2(Mr[0], h01.x, aR);  aR = ffma2(Mr[1], h01.y, aR);              \
    aR = ffma2(Mr[2], h23.x, aR);  aR = ffma2(Mr[3], h23.y, aR);              \
    aR = ffma2(Mr[4], h45.x, aR);  aR = ffma2(Mr[5], h45.y, aR);              \
    aR = ffma2(Mr[6], h67.x, aR);  aR = ffma2(Mr[7], h67.y, aR);              \
    aR = ffma2(Mr[8], h89.x, aR);  aR = ffma2(Mr[9], h89.y, aR);              \
    aH = ffma2(Wn[0], h01.x, aH);  aH = ffma2(Wn[1], h01.y, aH);              \
    aH = ffma2(Wn[2], h23.x, aH);  aH = ffma2(Wn[3], h23.y, aH);              \
    aH = ffma2(Wn[4], h45.x, aH);  aH = ffma2(Wn[5], h45.y, aH);              \
    aH = ffma2(Wn[6], h67.x, aH);  aH = ffma2(Wn[7], h67.y, aH);              \
    aH = ffma2(Wn[8], h89.x, aH);  aH = ffma2(Wn[9], h89.y, aH);              \
    aI = ffma2(Gn[0], h01.x, aI);  aI = ffma2(Gn[1], h01.y, aI);              \
    aI = ffma2(Gn[2], h23.x, aI);  aI = ffma2(Gn[3], h23.y, aI);              \
    aI = ffma2(Gn[4], h45.x, aI);  aI = ffma2(Gn[5], h45.y, aI);              \
    aI = ffma2(Gn[6], h67.x, aI);  aI = ffma2(Gn[7], h67.y, aI);              \
    aI = ffma2(Gn[8], h89.x, aI);  aI = ffma2(Gn[9], h89.y, aI);              \
    aZ = ffma2(Mz[0], h01.x, aZ);  aZ = ffma2(Mz[1], h01.y, aZ);              \
    aZ = ffma2(Mz[2], h23.x, aZ);  aZ = ffma2(Mz[3], h23.y, aZ);              \
    aZ = ffma2(Mz[4], h45.x, aZ);  aZ = ffma2(Mz[5], h45.y, aZ);              \
    aZ = ffma2(Mz[6], h67.x, aZ);  aZ = ffma2(Mz[7], h67.y, aZ);              \
    aZ = ffma2(Mz[8], h89.x, aZ);  aZ = ffma2(Mz[9], h89.y, aZ);              \
    aO = ffma2(L1[0], h01.x, aO);  aO = ffma2(L1[1], h01.y, aO);              \
    aO = ffma2(L1[2], h23.x, aO);  aO = ffma2(L1[3], h23.y, aO);              \
    aO = ffma2(L1[4], h45.x, aO);  aO = ffma2(L1[5], h45.y, aO);              \
    aO = ffma2(L1[6], h67.x, aO);  aO = ffma2(L1[7], h67.y, aO);              \
    aO = ffma2(L1[8], h89.x, aO);  aO = ffma2(L1[9], h89.y, aO);              \
    /* scalar epilogue: accumulator unpacks are register aliases (free) */    \
    float aRx, aRy, aZx, aZy, aIx, aIy, aHx, aHy, aOx, aOy;                   \
    funpack(aR, aRx, aRy); funpack(aZ, aZx, aZy);                             \
    funpack(aI, aIx, aIy); funpack(aH, aHx, aHy);                             \
    funpack(aO, aOx, aOy);                                                    \
    o0[OFS] = aOx; o1[OFS] = aOy;                                             \
    float rx = fmaf(0.5f, ftanha(aRx), 0.5f);                                 \
    float ry = fmaf(0.5f, ftanha(aRy), 0.5f);                                 \
    float nx = ftanha(fmaf(rx, aHx, aIx));                                    \
    float ny = ftanha(fmaf(ry, aHy, aIy));                                    \
    float zx = fmaf(0.5f, ftanha(aZx), 0.5f);                                 \
    float zy = fmaf(0.5f, ftanha(aZy), 0.5f);                                 \
    hx = fmaf(zx, hx - nx, nx);                                               \
    hy = fmaf(zy, hy - ny, ny);                                               \
    asm volatile("st.shared.v2.f32 [%0], {%1, %2};" ::                        \
                 "l"(WRP), "f"(hx), "f"(hy));                                 \
  } while (0)

    // t = 1..510 as 255 double-steps; then t = 511. After step 0, h is in buf1.
#pragma unroll 1
    for (int c = 0; c < 255; ++c) {
        STEP(rd1, wr0, 0);      // odd t: read buf1, write buf0
        STEP(rd0, wr1, -10);    // even t: read buf0, write buf1
        o0 -= 2 * HID;
        o1 -= 2 * HID;
    }
    STEP(rd1, wr0, 0);          // t = 511: read buf1, write buf0

    // epilogue: o_511 -> row 0 (h_512 sits in buffer 0)
    __syncwarp();
    {
        u64 aO = vl1b;
        const ulonglong2 h01 = rd0[0], h23 = rd0[1], h45 = rd0[2],
                         h67 = rd0[3], h89 = rd0[4];
        aO = ffma2(L1[0], h01.x, aO);  aO = ffma2(L1[1], h01.y, aO);
        aO = ffma2(L1[2], h23.x, aO);  aO = ffma2(L1[3], h23.y, aO);
        aO = ffma2(L1[4], h45.x, aO);  aO = ffma2(L1[5], h45.y, aO);
        aO = ffma2(L1[6], h67.x, aO);  aO = ffma2(L1[7], h67.y, aO);
        aO = ffma2(L1[8], h89.x, aO);  aO = ffma2(L1[9], h89.y, aO);
        float ox, oy;
        funpack(aO, ox, oy);
        o0[-10] = ox;
        o1[-10] = oy;
    }
#undef STEP
}

extern "C" void kernel_launch(void* const* d_in, const int* in_sizes, int n_in,
                              void* d_out, int out_size) {
    const float* hidden = (const float*)d_in[0];
    const float* w_ih   = (const float*)d_in[1];
    const float* w_hh   = (const float*)d_in[2];
    const float* b_ih   = (const float*)d_in[3];
    const float* b_hh   = (const float*)d_in[4];
    const float* l1_w   = (const float*)d_in[5];
    const float* l1_b   = (const float*)d_in[6];
    const float* l2_w   = (const float*)d_in[7];
    const float* l2_b   = (const float*)d_in[8];

    prep_kernel<<<1, 384>>>(w_ih, b_ih, l1_w, l1_b, l2_w, l2_b);
    gru_kernel<<<GRID, TPB>>>(hidden, w_hh, b_ih, b_hh, l1_w, l1_b, (float*)d_out);
}

// round 9
// speedup vs baseline: 1.7574x; 1.0157x over previous
#include <cuda_runtime.h>
#include <cstdint>

typedef unsigned long long u64;

// ---------- f32x2 / MUFU helpers ----------
__device__ __forceinline__ u64 ffma2(u64 a, u64 b, u64 c) {
    u64 d;
    asm("fma.rn.f32x2 %0, %1, %2, %3;" : "=l"(d) : "l"(a), "l"(b), "l"(c));
    return d;
}
__device__ __forceinline__ u64 fadd2(u64 a, u64 b) {
    u64 d;
    asm("add.rn.f32x2 %0, %1, %2;" : "=l"(d) : "l"(a), "l"(b));
    return d;
}
__device__ __forceinline__ u64 fpack(float x, float y) {
    u64 d;
    asm("mov.b64 %0, {%1, %2};" : "=l"(d) : "r"(__float_as_uint(x)), "r"(__float_as_uint(y)));
    return d;
}
__device__ __forceinline__ u64 fdup(float s) { return fpack(s, s); }
__device__ __forceinline__ void funpack(u64 v, float& x, float& y) {
    unsigned int a, b;
    asm("mov.b64 {%0, %1}, %2;" : "=r"(a), "=r"(b) : "l"(v));
    x = __uint_as_float(a);
    y = __uint_as_float(b);
}
__device__ __forceinline__ float fex2(float x) {
    float r; asm("ex2.approx.f32 %0, %1;" : "=f"(r) : "f"(x)); return r;
}
__device__ __forceinline__ float frcp(float x) {
    float r; asm("rcp.approx.f32 %0, %1;" : "=f"(r) : "f"(x)); return r;
}
__device__ __forceinline__ float ftanha(float x) {
    float r; asm("tanh.approx.f32 %0, %1;" : "=f"(r) : "f"(x)); return r;
}
__device__ __forceinline__ float fsig_exact(float x) {
    return frcp(1.0f + fex2(-1.44269504f * x));
}
__device__ __forceinline__ float ftanh_exact(float x) {
    return fmaf(-2.0f, frcp(1.0f + fex2(2.88539008f * x)), 1.0f);
}

// ---------- problem constants ----------
constexpr int BATCH = 8192;
constexpr int HID   = 10;
constexpr int STEPS = 512;
constexpr int PAIRS = BATCH / 2;       // 4096
constexpr int WPB   = 10;
constexpr int TPB   = WPB * 32;        // 320
constexpr int GRID  = 148;             // exactly 1 block / SM
constexpr int TOTW  = GRID * WPB;      // 1480 warps; pair slot s of warp g -> g + s*1480

// Folded weights: G = w_ih @ l2_w @ l1_w (30x10), d = w_ih@l2_b + (w_ih@l2_w)@l1_b + b_ih (30)
__device__ float g_G[300];
__device__ float g_d[30];
// sink rows for lanes without a valid batch pair (branch-free stores, full walk)
__device__ float g_sink[2 * STEPS * HID];

// ---------- prep kernel: fold the input path ----------
__global__ void prep_kernel(const float* __restrict__ w_ih,
                            const float* __restrict__ b_ih,
                            const float* __restrict__ l1_w,
                            const float* __restrict__ l1_b,
                            const float* __restrict__ l2_w,
                            const float* __restrict__ l2_b) {
    __shared__ float Wm[300]; // w_ih @ l2_w : (30,10)
    int t = threadIdx.x;
    if (t < 300) {
        int r = t / 10, m = t % 10;
        float s = 0.0f;
        for (int i = 0; i < 64; i++) s += w_ih[r * 64 + i] * l2_w[i * 10 + m];
        Wm[t] = s;
    }
    __syncthreads();
    if (t < 300) {
        int r = t / 10, k = t % 10;
        float g = 0.0f;
        for (int m = 0; m < 10; m++) g += Wm[r * 10 + m] * l1_w[m * 10 + k];
        g_G[t] = g;
    } else if (t < 330) {
        int r = t - 300;
        float s = b_ih[r];
        for (int i = 0; i < 64; i++) s += w_ih[r * 64 + i] * l2_b[i];
        for (int m = 0; m < 10; m++) s += Wm[r * 10 + m] * l1_b[m];
        g_d[r] = s;
    }
}

// ---------- main recurrence kernel ----------
// thread = (batch pair, gate dim j); pair = 2 batch elements in f32x2 for the
// five dot products. Scalar epilogue (unpacks are register aliases, packs
// would cost MOVs). 3 pairs per warp on lanes 0..29; lanes 30/31 shadow slot 0
// and store to a sink.
// NO per-step barrier: the hot loop is branch-free, the warp stays fully
// convergent, and the double-buffered STS -> LDS exchange is ordered by the
// per-SM LSU FIFO (store wavefront issued before the next step's load
// wavefronts). This removes WARPSYNC + its STS-drain from the 512-step serial
// chain. sigma(a)=0.5+0.5*tanh(a/2) with the 0.5 folded into r/z weights; all
// activations tanh.approx. aR/aH use split 5+5 chains to start the r-tanh
// ~12 cyc earlier.
__global__ void __launch_bounds__(TPB) gru_kernel(
    const float* __restrict__ hidden,
    const float* __restrict__ w_hh,
    const float* __restrict__ b_ih,
    const float* __restrict__ b_hh,
    const float* __restrict__ l1_w,
    const float* __restrict__ l1_b,
    float* __restrict__ out) {
    __shared__ alignas(16) u64 hsh[WPB][2][4][HID];

    const int lane = threadIdx.x & 31;
    const int w    = threadIdx.x >> 5;
    const int p    = lane / 10;            // 0..2 pair slots, 3 = spare lanes
    const int dd   = (p < 3) ? p : 0;      // spares read slot 0
    const int j    = lane - p * 10;        // 0..9 (spares: 0..1)
    const int g    = blockIdx.x * WPB + w;
    const int pairIdx = g + dd * TOTW;     // round-robin pair map
    const bool valid  = (p < 3) && (pairIdx < PAIRS);
    const int bb      = valid ? pairIdx * 2 : 0;

    // per-thread folded + scaled weight rows, duplicated into both f32x2 halves
    u64 Mr[10], Mz[10], Gn[10], Wn[10], L1[10];
#pragma unroll
    for (int k = 0; k < 10; k++) {
        Mr[k] = fdup(0.5f * (w_hh[j * 10 + k]        + g_G[j * 10 + k]));
        Mz[k] = fdup(0.5f * (w_hh[(10 + j) * 10 + k] + g_G[(10 + j) * 10 + k]));
        Gn[k] = fdup(g_G[(20 + j) * 10 + k]);
        Wn[k] = fdup(w_hh[(20 + j) * 10 + k]);
        L1[k] = fdup(l1_w[j * 10 + k]);
    }
    const u64 vbr  = fdup(0.5f * (b_hh[j]      + g_d[j]));
    const u64 vbz  = fdup(0.5f * (b_hh[10 + j] + g_d[10 + j]));
    const u64 vbin = fdup(g_d[20 + j]);
    const u64 vbhn = fdup(b_hh[20 + j]);
    const u64 vl1b = fdup(l1_b[j]);
    const u64 ZERO2 = 0ULL;

    float hx = hidden[bb * 10 + j];
    float hy = hidden[(bb + 1) * 10 + j];

    // smem addresses for this thread's h slot (write) and group row (read)
    u64* wr0 = &hsh[w][0][p][j];
    u64* wr1 = &hsh[w][1][p][j];
    const ulonglong2* rd0 = reinterpret_cast<const ulonglong2*>(&hsh[w][0][dd][0]);
    const ulonglong2* rd1 = reinterpret_cast<const ulonglong2*>(&hsh[w][1][dd][0]);

    *wr0 = fpack(hx, hy);
    __syncwarp();

    // peeled step 0: x0 = 0 -> gi = b_ih exactly (no G*h term). Exact activations.
    {
        float aRx = b_hh[j] + b_ih[j];
        float aZx = b_hh[10 + j] + b_ih[10 + j];
        float aRy = aRx, aZy = aZx;
        float aHx = b_hh[20 + j], aHy = aHx;
#pragma unroll
        for (int k = 0; k < 10; k++) {
            float kx, ky;
            funpack(hsh[w][0][dd][k], kx, ky);
            float wr = w_hh[j * 10 + k];
            float wz = w_hh[(10 + j) * 10 + k];
            float wn = w_hh[(20 + j) * 10 + k];
            aRx = fmaf(wr, kx, aRx); aRy = fmaf(wr, ky, aRy);
            aZx = fmaf(wz, kx, aZx); aZy = fmaf(wz, ky, aZy);
            aHx = fmaf(wn, kx, aHx); aHy = fmaf(wn, ky, aHy);
        }
        float inb = b_ih[20 + j];
        float rx = fsig_exact(aRx), ry = fsig_exact(aRy);
        float zx = fsig_exact(aZx), zy = fsig_exact(aZy);
        float nx = ftanh_exact(fmaf(rx, aHx, inb));
        float ny = ftanh_exact(fmaf(ry, aHy, inb));
        hx = fmaf(zx, hx - nx, nx);
        hy = fmaf(zy, hy - ny, ny);
    }
    asm volatile("st.shared.v2.f32 [%0], {%1, %2};" ::
                 "l"(wr1), "f"(hx), "f"(hy));
    __syncwarp();

    // REVERSE output: o_t -> row (511 - t); at iter t we emit o_{t-1}.
    // Invalid lanes walk sink rows (branch-free, same full walk, in-bounds).
    float* o0;
    float* o1;
    if (valid) {
        o0 = out + (size_t)bb * (STEPS * HID) + (STEPS - 1) * HID + j;
        o1 = out + (size_t)(bb + 1) * (STEPS * HID) + (STEPS - 1) * HID + j;
    } else {
        o0 = g_sink + (STEPS - 1) * HID + j;
        o1 = g_sink + STEPS * HID + (STEPS - 1) * HID + j;
    }

    // one GRU step: read buffer RD, write buffer WRP, store o at offset OFS.
    // No barrier: convergent warp, LSU FIFO orders STS before next LDS.
#define STEP(RD, WRP, OFS)                                                    \
  do {                                                                        \
    const ulonglong2 h01 = (RD)[0], h23 = (RD)[1], h45 = (RD)[2],             \
                     h67 = (RD)[3], h89 = (RD)[4];                            \
    u64 aR = vbr, aR2 = ZERO2, aH = vbhn, aH2 = ZERO2;                        \
    u64 aZ = vbz, aI = vbin, aO = vl1b;                                       \
    aR = ffma2(Mr[0], h01.x, aR);  aR2 = ffma2(Mr[1], h01.y, aR2);            \
    aR = ffma2(Mr[2], h23.x, aR);  aR2 = ffma2(Mr[3], h23.y, aR2);            \
    aR = ffma2(Mr[4], h45.x, aR);  aR2 = ffma2(Mr[5], h45.y, aR2);            \
    aR = ffma2(Mr[6], h67.x, aR);  aR2 = ffma2(Mr[7], h67.y, aR2);            \
    aR = ffma2(Mr[8], h89.x, aR);  aR2 = ffma2(Mr[9], h89.y, aR2);            \
    aR = fadd2(aR, aR2);                                                      \
    /* r-tanh as early as possible: it is the serial path */                  \
    float aRx, aRy;                                                           \
    funpack(aR, aRx, aRy);                                                    \
    const float tRx = ftanha(aRx), tRy = ftanha(aRy);                         \
    aH = ffma2(Wn[0], h01.x, aH);  aH2 = ffma2(Wn[1], h01.y, aH2);            \
    aH = ffma2(Wn[2], h23.x, aH);  aH2 = ffma2(Wn[3], h23.y, aH2);            \
    aH = ffma2(Wn[4], h45.x, aH);  aH2 = ffma2(Wn[5], h45.y, aH2);            \
    aH = ffma2(Wn[6], h67.x, aH);  aH2 = ffma2(Wn[7], h67.y, aH2);            \
    aH = ffma2(Wn[8], h89.x, aH);  aH2 = ffma2(Wn[9], h89.y, aH2);            \
    aH = fadd2(aH, aH2);                                                      \
    aI = ffma2(Gn[0], h01.x, aI);  aI = ffma2(Gn[1], h01.y, aI);              \
    aI = ffma2(Gn[2], h23.x, aI);  aI = ffma2(Gn[3], h23.y, aI);              \
    aI = ffma2(Gn[4], h45.x, aI);  aI = ffma2(Gn[5], h45.y, aI);              \
    aI = ffma2(Gn[6], h67.x, aI);  aI = ffma2(Gn[7], h67.y, aI);              \
    aI = ffma2(Gn[8], h89.x, aI);  aI = ffma2(Gn[9], h89.y, aI);              \
    float aIx, aIy, aHx, aHy;                                                 \
    funpack(aI, aIx, aIy); funpack(aH, aHx, aHy);                             \
    /* r = 0.5 + 0.5*tR ; arg = aI + r*aH */                                  \
    float rx = fmaf(0.5f, tRx, 0.5f);                                         \
    float ry = fmaf(0.5f, tRy, 0.5f);                                         \
    float nx = ftanha(fmaf(rx, aHx, aIx));                                    \
    float ny = ftanha(fmaf(ry, aHy, aIy));                                    \
    aZ = ffma2(Mz[0], h01.x, aZ);  aZ = ffma2(Mz[1], h01.y, aZ);              \
    aZ = ffma2(Mz[2], h23.x, aZ);  aZ = ffma2(Mz[3], h23.y, aZ);              \
    aZ = ffma2(Mz[4], h45.x, aZ);  aZ = ffma2(Mz[5], h45.y, aZ);              \
    aZ = ffma2(Mz[6], h67.x, aZ);  aZ = ffma2(Mz[7], h67.y, aZ);              \
    aZ = ffma2(Mz[8], h89.x, aZ);  aZ = ffma2(Mz[9], h89.y, aZ);              \
    aO = ffma2(L1[0], h01.x, aO);  aO = ffma2(L1[1], h01.y, aO);              \
    aO = ffma2(L1[2], h23.x, aO);  aO = ffma2(L1[3], h23.y, aO);              \
    aO = ffma2(L1[4], h45.x, aO);  aO = ffma2(L1[5], h45.y, aO);              \
    aO = ffma2(L1[6], h67.x, aO);  aO = ffma2(L1[7], h67.y, aO);              \
    aO = ffma2(L1[8], h89.x, aO);  aO = ffma2(L1[9], h89.y, aO);              \
    float aZx, aZy, aOx, aOy;                                                 \
    funpack(aZ, aZx, aZy); funpack(aO, aOx, aOy);                             \
    o0[OFS] = aOx; o1[OFS] = aOy;                                             \
    float zx = fmaf(0.5f, ftanha(aZx), 0.5f);                                 \
    float zy = fmaf(0.5f, ftanha(aZy), 0.5f);                                 \
    hx = fmaf(zx, hx - nx, nx);                                               \
    hy = fmaf(zy, hy - ny, ny);                                               \
    asm volatile("st.shared.v2.f32 [%0], {%1, %2};" ::                        \
                 "l"(WRP), "f"(hx), "f"(hy));                                 \
  } while (0)

    // t = 1..510 as 255 double-steps; then t = 511. After step 0, h is in buf1.
#pragma unroll 1
    for (int c = 0; c < 255; ++c) {
        STEP(rd1, wr0, 0);      // odd t: read buf1, write buf0
        STEP(rd0, wr1, -10);    // even t: read buf0, write buf1
        o0 -= 2 * HID;
        o1 -= 2 * HID;
    }
    STEP(rd1, wr0, 0);          // t = 511: read buf1, write buf0

    // epilogue: o_511 -> row 0 (h_512 sits in buffer 0)
    __syncwarp();
    {
        u64 aO = vl1b;
        const ulonglong2 h01 = rd0[0], h23 = rd0[1], h45 = rd0[2],
                         h67 = rd0[3], h89 = rd0[4];
        aO = ffma2(L1[0], h01.x, aO);  aO = ffma2(L1[1], h01.y, aO);
        aO = ffma2(L1[2], h23.x, aO);  aO = ffma2(L1[3], h23.y, aO);
        aO = ffma2(L1[4], h45.x, aO);  aO = ffma2(L1[5], h45.y, aO);
        aO = ffma2(L1[6], h67.x, aO);  aO = ffma2(L1[7], h67.y, aO);
        aO = ffma2(L1[8], h89.x, aO);  aO = ffma2(L1[9], h89.y, aO);
        float ox, oy;
        funpack(aO, ox, oy);
        o0[-10] = ox;
        o1[-10] = oy;
    }
#undef STEP
}

extern "C" void kernel_launch(void* const* d_in, const int* in_sizes, int n_in,
                              void* d_out, int out_size) {
    const float* hidden = (const float*)d_in[0];
    const float* w_ih   = (const float*)d_in[1];
    const float* w_hh   = (const float*)d_in[2];
    const float* b_ih   = (const float*)d_in[3];
    const float* b_hh   = (const float*)d_in[4];
    const float* l1_w   = (const float*)d_in[5];
    const float* l1_b   = (const float*)d_in[6];
    const float* l2_w   = (const float*)d_in[7];
    const float* l2_b   = (const float*)d_in[8];

    prep_kernel<<<1, 384>>>(w_ih, b_ih, l1_w, l1_b, l2_w, l2_b);
    gru_kernel<<<GRID, TPB>>>(hidden, w_hh, b_ih, b_hh, l1_w, l1_b, (float*)d_out);
}